// round 2
// baseline (speedup 1.0000x reference)
#include <cuda_runtime.h>
#include <math.h>

#define B   128
#define T   256
#define DIN 512
#define H   1024
#define S   128
#define DH  1024

// ---- scratch (device globals; no allocations allowed) ----
__device__ float  g_h[2][B * H];              // double-buffered hidden state
__device__ float  g_c[B * H];                 // cell state (elementwise-owned, safe in place)
__device__ float  g_z[(T + 1) * B * S];       // z slots: slot 0 = zeros, slot t+1 = z after step t
__device__ float  g_hid[(size_t)B * T * DH];  // decoder intermediate (134 MB)
__device__ double g_klpart[T * 128];          // deterministic KL partials

__device__ __forceinline__ float sigf(float x) { return 1.0f / (1.0f + expf(-x)); }

// ---------------------------------------------------------------------------
// init: zero recurrent state each replay (graph is re-run; state must reset)
// ---------------------------------------------------------------------------
__global__ void init_kernel() {
    int stride = gridDim.x * blockDim.x;
    int tid0 = blockIdx.x * blockDim.x + threadIdx.x;
    float* hb = (float*)g_h;
    for (int i = tid0; i < 2 * B * H; i += stride) hb[i] = 0.0f;
    for (int i = tid0; i < B * H; i += stride) g_c[i] = 0.0f;
    for (int i = tid0; i < B * S; i += stride) g_z[i] = 0.0f;
}

// ---------------------------------------------------------------------------
// K1: gates = z_prev@W_ih^T + h@W_hh^T + b  (gate-interleaved tiles), fused LSTM
// grid: 128 CTAs (each owns 8 hidden units x 4 gates = 32 output cols, M=128)
// ---------------------------------------------------------------------------
__global__ __launch_bounds__(256) void lstm_kernel(
    const float* __restrict__ zprev, const float* __restrict__ hin,
    float* __restrict__ hout,
    const float* __restrict__ Wih, const float* __restrict__ Whh,
    const float* __restrict__ bih, const float* __restrict__ bhh)
{
    __shared__ float As[32][128];   // A tile, transposed: As[k][b]
    __shared__ float Ws[32][32];    // W tile, swizzled groups of 4 gates

    const int tid = threadIdx.x;
    const int tx = tid & 7;          // hidden unit within tile (jj)
    const int ty = tid >> 3;         // batch group (4 rows each)
    const int hbase = blockIdx.x * 8;

    float acc[4][4];
    #pragma unroll
    for (int g = 0; g < 4; g++)
        #pragma unroll
        for (int b2 = 0; b2 < 4; b2++) acc[g][b2] = 0.0f;

    // W loader mapping (fixed per thread)
    const int cw = tid >> 3;            // 0..31 column id
    const int g_w = cw & 3;             // gate
    const int jj_w = cw >> 2;           // hidden unit in tile
    const int klw = (tid & 7) * 4;      // k within block
    const int wrow = g_w * H + hbase + jj_w;
    const int colg = (jj_w ^ (klw >> 2)) * 4 + g_w;   // XOR swizzle (conflict-free)

    #pragma unroll
    for (int phase = 0; phase < 2; phase++) {
        const float* A = phase ? hin : zprev;
        const float* W = phase ? Whh : Wih;
        const int K = phase ? H : S;
        for (int k0 = 0; k0 < K; k0 += 32) {
            #pragma unroll
            for (int i = 0; i < 4; i++) {
                int idx = tid + i * 256;
                int bb = idx & 127, kg = idx >> 7;
                float4 v = *(const float4*)(A + (size_t)bb * K + k0 + kg * 4);
                As[kg * 4 + 0][bb] = v.x; As[kg * 4 + 1][bb] = v.y;
                As[kg * 4 + 2][bb] = v.z; As[kg * 4 + 3][bb] = v.w;
            }
            {
                float4 v = *(const float4*)(W + (size_t)wrow * K + k0 + klw);
                Ws[klw + 0][colg] = v.x; Ws[klw + 1][colg] = v.y;
                Ws[klw + 2][colg] = v.z; Ws[klw + 3][colg] = v.w;
            }
            __syncthreads();
            #pragma unroll
            for (int k = 0; k < 32; k++) {
                float4 a = *(const float4*)&As[k][ty * 4];
                float4 w = *(const float4*)&Ws[k][(tx ^ (k >> 2)) * 4];
                float av[4] = {a.x, a.y, a.z, a.w};
                float wv[4] = {w.x, w.y, w.z, w.w};
                #pragma unroll
                for (int g = 0; g < 4; g++)
                    #pragma unroll
                    for (int b2 = 0; b2 < 4; b2++)
                        acc[g][b2] = fmaf(wv[g], av[b2], acc[g][b2]);
            }
            __syncthreads();
        }
    }

    // fused LSTM pointwise: this thread owns hidden unit j for 4 batch rows
    const int j = hbase + tx;
    const float bI = bih[j] + bhh[j];
    const float bF = bih[H + j] + bhh[H + j];
    const float bG = bih[2 * H + j] + bhh[2 * H + j];
    const float bO = bih[3 * H + j] + bhh[3 * H + j];
    #pragma unroll
    for (int b2 = 0; b2 < 4; b2++) {
        int b = ty * 4 + b2;
        float ig = sigf(acc[0][b2] + bI);
        float fg = sigf(acc[1][b2] + bF);
        float gg = tanhf(acc[2][b2] + bG);
        float og = sigf(acc[3][b2] + bO);
        float cn = fg * g_c[b * H + j] + ig * gg;
        g_c[b * H + j] = cn;
        hout[b * H + j] = og * tanhf(cn);
    }
}

// ---------------------------------------------------------------------------
// K2: posterior heads + reparam + KL partial.
// grid: 128 CTAs = 64 s-pairs x 2 batch halves; thread = one (b, s, mean|lv)
// ---------------------------------------------------------------------------
__global__ __launch_bounds__(256) void post_kernel(
    const float* __restrict__ x, const float* __restrict__ noise,
    const float* __restrict__ h, float* __restrict__ zout,
    const float* __restrict__ Wm, const float* __restrict__ bm,
    const float* __restrict__ Wv, const float* __restrict__ bv, int t)
{
    __shared__ float Wrows[4][DIN + H];  // 4 rows (2 s x {Wm,Wv}) staged
    __shared__ float vals[256];
    __shared__ double klred[8];

    const int tid = threadIdx.x;
    const int bx = blockIdx.x;
    const int sgrp = bx >> 1, bgrp = bx & 1;

    #pragma unroll
    for (int i = 0; i < 6; i++) {
        int idx = tid + i * 256;        // 1536 float4 ids total
        int r = idx / 384;
        int k4 = idx - r * 384;
        const float* src = (r & 1) ? Wv : Wm;
        int srow = sgrp * 2 + (r >> 1);
        *(float4*)&Wrows[r][k4 * 4] =
            *(const float4*)(src + (size_t)srow * (DIN + H) + k4 * 4);
    }
    __syncthreads();

    const int b_l = tid >> 2, s_l = (tid >> 1) & 1, which = tid & 1;
    const int b = bgrp * 64 + b_l, s = sgrp * 2 + s_l;
    const float* Wr = Wrows[s_l * 2 + which];
    const float* px = x + (size_t)b * T * DIN + (size_t)t * DIN;
    const float* ph = h + (size_t)b * H;

    float acc = which ? bv[s] : bm[s];
    #pragma unroll 4
    for (int k4 = 0; k4 < DIN / 4; k4++) {
        float4 p = *(const float4*)(px + k4 * 4);
        float4 w = *(const float4*)(Wr + k4 * 4);
        acc = fmaf(p.x, w.x, acc); acc = fmaf(p.y, w.y, acc);
        acc = fmaf(p.z, w.z, acc); acc = fmaf(p.w, w.w, acc);
    }
    #pragma unroll 4
    for (int k4 = 0; k4 < H / 4; k4++) {
        float4 p = *(const float4*)(ph + k4 * 4);
        float4 w = *(const float4*)(Wr + DIN + k4 * 4);
        acc = fmaf(p.x, w.x, acc); acc = fmaf(p.y, w.y, acc);
        acc = fmaf(p.z, w.z, acc); acc = fmaf(p.w, w.w, acc);
    }
    vals[tid] = acc;
    __syncthreads();

    float klterm = 0.0f;
    if (which == 0) {
        float mean = acc, lv = vals[tid | 1];
        float sd = expf(0.5f * lv);
        float nt = noise[(size_t)b * T * S + (size_t)t * S + s];
        zout[b * S + s] = nt * sd + mean;
        klterm = expf(lv) + mean * mean - 0.5f * lv - 0.5f;
    }
    #pragma unroll
    for (int off = 16; off; off >>= 1)
        klterm += __shfl_down_sync(0xffffffffu, klterm, off);
    if ((tid & 31) == 0) klred[tid >> 5] = (double)klterm;
    __syncthreads();
    if (tid == 0) {
        double ssum = 0.0;
        #pragma unroll
        for (int w = 0; w < 8; w++) ssum += klred[w];
        g_klpart[t * 128 + bx] = ssum;
    }
}

// ---------------------------------------------------------------------------
// Decoder GEMM1: hid = relu(Z @ Wd1^T + bd1), Z rows = g_z slots 1..T
// grid: (16 n-tiles of 64, 256 row-tiles of 128)
// ---------------------------------------------------------------------------
__global__ __launch_bounds__(256) void dec_gemm1(
    const float* __restrict__ Wd1, const float* __restrict__ bd1)
{
    __shared__ float As[32][128];
    __shared__ float Ws[32][64];
    const int tid = threadIdx.x;
    const int tx = tid & 15, ty = tid >> 4;
    const int nb = blockIdx.x * 64;
    const int rb = blockIdx.y * 128;
    const float* A = g_z + B * S + (size_t)rb * S;   // ld = 128

    float acc[8][4];
    #pragma unroll
    for (int r = 0; r < 8; r++)
        #pragma unroll
        for (int c = 0; c < 4; c++) acc[r][c] = 0.0f;

    for (int k0 = 0; k0 < S; k0 += 32) {
        #pragma unroll
        for (int i = 0; i < 4; i++) {
            int idx = tid + i * 256;
            int rr = idx & 127, kg = idx >> 7;
            float4 v = *(const float4*)(A + (size_t)rr * S + k0 + kg * 4);
            As[kg * 4 + 0][rr] = v.x; As[kg * 4 + 1][rr] = v.y;
            As[kg * 4 + 2][rr] = v.z; As[kg * 4 + 3][rr] = v.w;
        }
        #pragma unroll
        for (int i = 0; i < 2; i++) {
            int idx = tid + i * 256;
            int k4 = idx & 7, n_l = idx >> 3;
            float4 v = *(const float4*)(Wd1 + (size_t)(nb + n_l) * S + k0 + k4 * 4);
            int cg = (((n_l >> 2) ^ k4)) * 4 + (n_l & 3);
            Ws[k4 * 4 + 0][cg] = v.x; Ws[k4 * 4 + 1][cg] = v.y;
            Ws[k4 * 4 + 2][cg] = v.z; Ws[k4 * 4 + 3][cg] = v.w;
        }
        __syncthreads();
        #pragma unroll
        for (int k = 0; k < 32; k++) {
            float4 a0 = *(const float4*)&As[k][ty * 8];
            float4 a1 = *(const float4*)&As[k][ty * 8 + 4];
            float4 w  = *(const float4*)&Ws[k][(tx ^ (k >> 2)) * 4];
            float av[8] = {a0.x, a0.y, a0.z, a0.w, a1.x, a1.y, a1.z, a1.w};
            float wv[4] = {w.x, w.y, w.z, w.w};
            #pragma unroll
            for (int r = 0; r < 8; r++)
                #pragma unroll
                for (int c = 0; c < 4; c++)
                    acc[r][c] = fmaf(av[r], wv[c], acc[r][c]);
        }
        __syncthreads();
    }
    #pragma unroll
    for (int r = 0; r < 8; r++) {
        int row = rb + ty * 8 + r;
        int n0 = nb + tx * 4;
        float4 o;
        o.x = fmaxf(acc[r][0] + bd1[n0 + 0], 0.0f);
        o.y = fmaxf(acc[r][1] + bd1[n0 + 1], 0.0f);
        o.z = fmaxf(acc[r][2] + bd1[n0 + 2], 0.0f);
        o.w = fmaxf(acc[r][3] + bd1[n0 + 3], 0.0f);
        *(float4*)&g_hid[(size_t)row * DH + n0] = o;
    }
}

// ---------------------------------------------------------------------------
// Decoder GEMM2: x_hat = hid @ Wd2^T + bd2 -> d_out [B,T,DIN]
// grid: (8 n-tiles of 64, 256 row-tiles of 128)
// ---------------------------------------------------------------------------
__global__ __launch_bounds__(256) void dec_gemm2(
    const float* __restrict__ Wd2, const float* __restrict__ bd2,
    float* __restrict__ out)
{
    __shared__ float As[32][128];
    __shared__ float Ws[32][64];
    const int tid = threadIdx.x;
    const int tx = tid & 15, ty = tid >> 4;
    const int nb = blockIdx.x * 64;
    const int rb = blockIdx.y * 128;
    const float* A = g_hid + (size_t)rb * DH;   // ld = 1024

    float acc[8][4];
    #pragma unroll
    for (int r = 0; r < 8; r++)
        #pragma unroll
        for (int c = 0; c < 4; c++) acc[r][c] = 0.0f;

    for (int k0 = 0; k0 < DH; k0 += 32) {
        #pragma unroll
        for (int i = 0; i < 4; i++) {
            int idx = tid + i * 256;
            int rr = idx & 127, kg = idx >> 7;
            float4 v = *(const float4*)(A + (size_t)rr * DH + k0 + kg * 4);
            As[kg * 4 + 0][rr] = v.x; As[kg * 4 + 1][rr] = v.y;
            As[kg * 4 + 2][rr] = v.z; As[kg * 4 + 3][rr] = v.w;
        }
        #pragma unroll
        for (int i = 0; i < 2; i++) {
            int idx = tid + i * 256;
            int k4 = idx & 7, n_l = idx >> 3;
            float4 v = *(const float4*)(Wd2 + (size_t)(nb + n_l) * DH + k0 + k4 * 4);
            int cg = (((n_l >> 2) ^ k4)) * 4 + (n_l & 3);
            Ws[k4 * 4 + 0][cg] = v.x; Ws[k4 * 4 + 1][cg] = v.y;
            Ws[k4 * 4 + 2][cg] = v.z; Ws[k4 * 4 + 3][cg] = v.w;
        }
        __syncthreads();
        #pragma unroll
        for (int k = 0; k < 32; k++) {
            float4 a0 = *(const float4*)&As[k][ty * 8];
            float4 a1 = *(const float4*)&As[k][ty * 8 + 4];
            float4 w  = *(const float4*)&Ws[k][(tx ^ (k >> 2)) * 4];
            float av[8] = {a0.x, a0.y, a0.z, a0.w, a1.x, a1.y, a1.z, a1.w};
            float wv[4] = {w.x, w.y, w.z, w.w};
            #pragma unroll
            for (int r = 0; r < 8; r++)
                #pragma unroll
                for (int c = 0; c < 4; c++)
                    acc[r][c] = fmaf(av[r], wv[c], acc[r][c]);
        }
        __syncthreads();
    }
    #pragma unroll
    for (int r = 0; r < 8; r++) {
        int row = rb + ty * 8 + r;       // row = t*128 + b
        int tt = row >> 7, bb = row & 127;
        int n0 = nb + tx * 4;
        float4 o;
        o.x = acc[r][0] + bd2[n0 + 0];
        o.y = acc[r][1] + bd2[n0 + 1];
        o.z = acc[r][2] + bd2[n0 + 2];
        o.w = acc[r][3] + bd2[n0 + 3];
        *(float4*)&out[(size_t)bb * T * DIN + (size_t)tt * DIN + n0] = o;
    }
}

// ---------------------------------------------------------------------------
// Final KL reduction (deterministic, fixed order)
// ---------------------------------------------------------------------------
__global__ void kl_kernel(float* __restrict__ out) {
    __shared__ double red[256];
    int tid = threadIdx.x;
    double ssum = 0.0;
    for (int i = tid; i < T * 128; i += 256) ssum += g_klpart[i];
    red[tid] = ssum;
    __syncthreads();
    for (int off = 128; off; off >>= 1) {
        if (tid < off) red[tid] += red[tid + off];
        __syncthreads();
    }
    if (tid == 0) out[(size_t)B * T * DIN] = (float)red[0];
}

// ---------------------------------------------------------------------------
extern "C" void kernel_launch(void* const* d_in, const int* in_sizes, int n_in,
                              void* d_out, int out_size)
{
    const float* x     = (const float*)d_in[0];
    const float* noise = (const float*)d_in[1];
    const float* Wih   = (const float*)d_in[2];
    const float* Whh   = (const float*)d_in[3];
    const float* bih   = (const float*)d_in[4];
    const float* bhh   = (const float*)d_in[5];
    const float* Wm    = (const float*)d_in[6];
    const float* bm    = (const float*)d_in[7];
    const float* Wv    = (const float*)d_in[8];
    const float* bv    = (const float*)d_in[9];
    const float* Wd1   = (const float*)d_in[10];
    const float* bd1   = (const float*)d_in[11];
    const float* Wd2   = (const float*)d_in[12];
    const float* bd2   = (const float*)d_in[13];
    float* out = (float*)d_out;

    float *p_z, *p_h;
    cudaGetSymbolAddress((void**)&p_z, g_z);
    cudaGetSymbolAddress((void**)&p_h, g_h);

    init_kernel<<<256, 256>>>();

    for (int t = 0; t < T; t++) {
        lstm_kernel<<<128, 256>>>(p_z + (size_t)t * B * S,
                                  p_h + (size_t)(t & 1) * B * H,
                                  p_h + (size_t)((t + 1) & 1) * B * H,
                                  Wih, Whh, bih, bhh);
        post_kernel<<<128, 256>>>(x, noise,
                                  p_h + (size_t)((t + 1) & 1) * B * H,
                                  p_z + (size_t)(t + 1) * B * S,
                                  Wm, bm, Wv, bv, t);
    }
    dec_gemm1<<<dim3(16, 256), 256>>>(Wd1, bd1);
    dec_gemm2<<<dim3(8, 256), 256>>>(Wd2, bd2, out);
    kl_kernel<<<1, 256>>>(out);
}

// round 4
// speedup vs baseline: 2.9183x; 2.9183x over previous
#include <cuda_runtime.h>
#include <cstdint>

#define B   128
#define T   256
#define DIN 512
#define H   1024
#define S   128
#define DH  1024

// ---- scratch (device globals; no allocations allowed) ----
__device__ float  g_h[2][B * H];                 // hidden (tf32-rounded)
__device__ float  g_c[B * H];                    // cell (fp32)
__device__ float  g_z[(T + 1) * B * S];          // z slots (tf32-rounded); slot0 = zeros
__device__ float  g_hid[(size_t)B * T * DH];     // decoder mid (tf32-rounded)
__device__ float  g_P[(size_t)B * T * 256];      // precomputed x-part of posterior (fp32)
__device__ float  g_xr[(size_t)B * T * DIN];     // x rounded to tf32
__device__ float  g_Wp[4096 * 1152];             // gate-interleaved LSTM W (tf32)
__device__ float  g_bp[4096];                    // bih+bhh gate-interleaved (fp32)
__device__ float  g_Wmv[256 * 1536];             // rows 2s=Wm[s],2s+1=Wv[s] (tf32)
__device__ float  g_Wd1r[DH * S];                // tf32
__device__ float  g_Wd2r[DIN * DH];              // tf32
__device__ double g_klpart[T * 32];

// ======================= helpers =======================
__device__ __forceinline__ uint32_t smem_u32(const void* p) {
    uint32_t a;
    asm("{ .reg .u64 t; cvta.to.shared.u64 t, %1; cvt.u32.u64 %0, t; }" : "=r"(a) : "l"(p));
    return a;
}
__device__ __forceinline__ float t32(float x) {
    float r; asm("cvt.rna.tf32.f32 %0, %1;" : "=f"(r) : "f"(x)); return r;
}
__device__ __forceinline__ void cpa(uint32_t dst, const void* src) {
    asm volatile("cp.async.cg.shared.global [%0], [%1], 16;" :: "r"(dst), "l"(src) : "memory");
}
#define CP_COMMIT() asm volatile("cp.async.commit_group;" ::: "memory")
#define CP_WAIT1()  asm volatile("cp.async.wait_group 1;" ::: "memory")
#define CP_WAIT0()  asm volatile("cp.async.wait_group 0;" ::: "memory")

__device__ __forceinline__ void ldsm4(uint32_t (&r)[4], uint32_t a) {
    asm volatile("ldmatrix.sync.aligned.m8n8.x4.shared.b16 {%0,%1,%2,%3}, [%4];"
                 : "=r"(r[0]), "=r"(r[1]), "=r"(r[2]), "=r"(r[3]) : "r"(a));
}
__device__ __forceinline__ void ldsm2(uint32_t (&r)[2], uint32_t a) {
    asm volatile("ldmatrix.sync.aligned.m8n8.x2.shared.b16 {%0,%1}, [%2];"
                 : "=r"(r[0]), "=r"(r[1]) : "r"(a));
}
__device__ __forceinline__ void mma8(float (&d)[4], const uint32_t (&a)[4], const uint32_t* b) {
    asm volatile("mma.sync.aligned.m16n8k8.row.col.f32.tf32.tf32.f32 "
        "{%0,%1,%2,%3}, {%4,%5,%6,%7}, {%8,%9}, {%0,%1,%2,%3};"
        : "+f"(d[0]), "+f"(d[1]), "+f"(d[2]), "+f"(d[3])
        : "r"(a[0]), "r"(a[1]), "r"(a[2]), "r"(a[3]), "r"(b[0]), "r"(b[1]));
}
__device__ __forceinline__ float fsig(float x) {
    float xc = fminf(fmaxf(x, -30.f), 30.f);
    return __fdividef(1.f, 1.f + __expf(-xc));
}
__device__ __forceinline__ float ftanh(float x) {
    float xc = fminf(fmaxf(x, -15.f), 15.f);
    float e = __expf(-2.f * xc);
    return __fdividef(1.f - e, 1.f + e);
}

// ======================= tf32 GEMM mainloop =======================
// C[128, NT] += A[128, 32*nchunks] @ W[NT, 32*nchunks]^T.  8 warps = NWM x NWN.
// A rows from a0 (chunks < split, stride sa0) then a1 (stride sa1). Pitch 36 floats.
template<int NT, int NWM, int NWN, int MT, int NTT>
__device__ __forceinline__ void gemm_main(
    float (&acc)[MT][NTT][4],
    const float* a0, int sa0, int split, const float* a1, int sa1,
    const float* wsrc, int sw, int nchunks)
{
    extern __shared__ float smem[];
    float* As = smem;                  // [2][128*36]
    float* Ws = smem + 2 * 128 * 36;   // [2][NT*36]
    const int tid = threadIdx.x;
    const int t = tid & 31, w = tid >> 5;
    const int wm = w % NWM, wn = w / NWM;
    const int m0 = wm * (128 / NWM), n0 = wn * (NT / NWN);

    #pragma unroll
    for (int mt = 0; mt < MT; mt++)
        #pragma unroll
        for (int nt = 0; nt < NTT; nt++)
            #pragma unroll
            for (int q = 0; q < 4; q++) acc[mt][nt][q] = 0.f;

    const uint32_t as_b = smem_u32(As), ws_b = smem_u32(Ws);

    // ldmatrix per-thread byte offsets (within a buffer, before +j*32)
    uint32_t aoff[MT];
    #pragma unroll
    for (int mt = 0; mt < MT; mt++) {
        int row = m0 + mt * 16 + (t & 7) + ((t >> 3) & 1) * 8;
        aoff[mt] = (uint32_t)(row * 36 + (t >> 4) * 4) * 4u;
    }
    constexpr int NP = (NTT + 1) / 2;
    uint32_t woff[NP];
    if constexpr (NTT == 1) {
        int row = n0 + (t & 7);
        woff[0] = (uint32_t)(row * 36 + ((t >> 3) & 1) * 4) * 4u;
    } else {
        #pragma unroll
        for (int p = 0; p < NP; p++) {
            int row = n0 + p * 16 + (t & 7) + ((t >> 4) & 1) * 8;
            woff[p] = (uint32_t)(row * 36 + ((t >> 3) & 1) * 4) * 4u;
        }
    }

    constexpr int WU = NT * 8;               // 16B units in W chunk
    constexpr int WI = (WU + 255) / 256;

    auto issue = [&](int c) {
        int buf = c & 1;
        const float* ap; int sa;
        if (c < split) { ap = a0 + c * 32;           sa = sa0; }
        else           { ap = a1 + (c - split) * 32; sa = sa1; }
        uint32_t ad = as_b + (uint32_t)buf * (128 * 36 * 4);
        #pragma unroll
        for (int i = 0; i < 4; i++) {
            int u = tid + i * 256;
            int row = u >> 3, kc = (u & 7) * 4;
            cpa(ad + (uint32_t)(row * 36 + kc) * 4u, ap + (size_t)row * sa + kc);
        }
        const float* wp = wsrc + c * 32;
        uint32_t wd = ws_b + (uint32_t)buf * (NT * 36 * 4);
        #pragma unroll
        for (int i = 0; i < WI; i++) {
            int u = tid + i * 256;
            if ((WU % 256 == 0) || (u < WU)) {
                int row = u >> 3, kc = (u & 7) * 4;
                cpa(wd + (uint32_t)(row * 36 + kc) * 4u, wp + (size_t)row * sw + kc);
            }
        }
        CP_COMMIT();
    };

    issue(0);
    for (int c = 0; c < nchunks; c++) {
        __syncthreads();                                // prev compute done everywhere
        if (c + 1 < nchunks) { issue(c + 1); CP_WAIT1(); }
        else                 { CP_WAIT0(); }
        __syncthreads();                                // chunk c visible to all
        uint32_t ab = as_b + (uint32_t)(c & 1) * (128 * 36 * 4);
        uint32_t wb = ws_b + (uint32_t)(c & 1) * (NT * 36 * 4);
        #pragma unroll
        for (int j = 0; j < 4; j++) {
            uint32_t afr[MT][4];
            #pragma unroll
            for (int mt = 0; mt < MT; mt++) ldsm4(afr[mt], ab + aoff[mt] + j * 32);
            uint32_t bfr[NTT][2];
            if constexpr (NTT == 1) {
                uint32_t r2[2];
                ldsm2(r2, wb + woff[0] + j * 32);
                bfr[0][0] = r2[0]; bfr[0][1] = r2[1];
            } else {
                #pragma unroll
                for (int p = 0; p < NP; p++) {
                    uint32_t r4[4];
                    ldsm4(r4, wb + woff[p] + j * 32);
                    bfr[2 * p][0] = r4[0]; bfr[2 * p][1] = r4[1];
                    bfr[2 * p + 1][0] = r4[2]; bfr[2 * p + 1][1] = r4[3];
                }
            }
            #pragma unroll
            for (int mt = 0; mt < MT; mt++)
                #pragma unroll
                for (int nt = 0; nt < NTT; nt++)
                    mma8(acc[mt][nt], afr[mt], bfr[nt]);
        }
    }
    __syncthreads();
}

// ======================= init / prepack =======================
__global__ void init_kernel() {
    int stride = gridDim.x * blockDim.x;
    int t0 = blockIdx.x * blockDim.x + threadIdx.x;
    for (int i = t0; i < B * H; i += stride) { g_h[0][i] = 0.f; g_c[i] = 0.f; }
    for (int i = t0; i < B * S; i += stride) g_z[i] = 0.f;
}

__global__ void prepack_kernel(
    const float* __restrict__ x,
    const float* __restrict__ Wih, const float* __restrict__ Whh,
    const float* __restrict__ bih, const float* __restrict__ bhh,
    const float* __restrict__ Wm, const float* __restrict__ Wv,
    const float* __restrict__ Wd1, const float* __restrict__ Wd2)
{
    size_t stride = (size_t)gridDim.x * blockDim.x;
    size_t t0 = (size_t)blockIdx.x * blockDim.x + threadIdx.x;
    for (size_t i = t0; i < (size_t)4096 * 1152; i += stride) {
        int n = (int)(i / 1152), k = (int)(i % 1152);
        int j = n >> 2, g = n & 3;
        float v = (k < S) ? Wih[(size_t)(g * H + j) * S + k]
                          : Whh[(size_t)(g * H + j) * H + (k - S)];
        g_Wp[i] = t32(v);
    }
    for (size_t i = t0; i < (size_t)256 * 1536; i += stride) {
        int n = (int)(i / 1536), k = (int)(i % 1536);
        const float* src = (n & 1) ? Wv : Wm;
        g_Wmv[i] = t32(src[(size_t)(n >> 1) * 1536 + k]);
    }
    for (size_t i = t0; i < (size_t)DH * S; i += stride)   g_Wd1r[i] = t32(Wd1[i]);
    for (size_t i = t0; i < (size_t)DIN * DH; i += stride) g_Wd2r[i] = t32(Wd2[i]);
    for (size_t i = t0; i < (size_t)B * T * DIN; i += stride) g_xr[i] = t32(x[i]);
    for (size_t i = t0; i < 4096; i += stride) {
        int j = (int)(i >> 2), g = (int)(i & 3);
        g_bp[i] = bih[g * H + j] + bhh[g * H + j];
    }
}

// ======================= LSTM step: 128 CTAs x N32, fused pointwise =======================
__global__ __launch_bounds__(256) void lstm_k(
    const float* __restrict__ zt, const float* __restrict__ hin, float* __restrict__ hout)
{
    float acc[2][2][4];
    gemm_main<32, 4, 2, 2, 2>(acc, zt, S, 4, hin, H,
                              g_Wp + (size_t)blockIdx.x * 32 * 1152, 1152, 36);

    const int tid = threadIdx.x, t = tid & 31, w = tid >> 5;
    const int wm = w & 3, wn = w >> 2;
    const int m0 = wm * 32, n0 = wn * 16;
    const bool even = (t & 1) == 0;

    #pragma unroll
    for (int mt = 0; mt < 2; mt++)
        #pragma unroll
        for (int nt = 0; nt < 2; nt++)
            #pragma unroll
            for (int rh = 0; rh < 2; rh++) {
                float v0 = acc[mt][nt][rh * 2], v1 = acc[mt][nt][rh * 2 + 1];
                float p0 = __shfl_xor_sync(0xffffffffu, v0, 1);
                float p1 = __shfl_xor_sync(0xffffffffu, v1, 1);
                if (even) {
                    int lc = n0 + nt * 8 + 2 * (t & 3);        // multiple of 4
                    int pcb = blockIdx.x * 32 + lc;
                    int j = pcb >> 2;
                    float4 bb = *(const float4*)&g_bp[pcb];
                    int b = m0 + mt * 16 + (t >> 2) + rh * 8;
                    float cold = g_c[b * H + j];
                    float i_ = fsig(v0 + bb.x);
                    float f_ = fsig(v1 + bb.y);
                    float gg = ftanh(p0 + bb.z);
                    float o_ = fsig(p1 + bb.w);
                    float cn = f_ * cold + i_ * gg;
                    g_c[b * H + j] = cn;
                    hout[b * H + j] = t32(o_ * ftanh(cn));
                }
            }
}

// ======================= posterior step: 32 CTAs x N8 (h-part only) =======================
__global__ __launch_bounds__(256) void post_k(
    const float* __restrict__ noise,
    const float* __restrict__ bm, const float* __restrict__ bv,
    const float* __restrict__ hin, int ts)
{
    float acc[1][1][4];
    gemm_main<8, 8, 1, 1, 1>(acc, hin, H, 1 << 28, hin, H,
                             g_Wmv + (size_t)blockIdx.x * 8 * 1536 + 512, 1536, 32);

    __shared__ double klw[8];
    const int tid = threadIdx.x, t = tid & 31, w = tid >> 5;
    const int m0 = w * 16, tig = t & 3;
    const int s = blockIdx.x * 4 + tig;
    const float bms = bm[s], bvs = bv[s];
    float kl = 0.f;
    #pragma unroll
    for (int rh = 0; rh < 2; rh++) {
        int b = m0 + (t >> 2) + rh * 8;
        const float* pp = g_P + ((size_t)b * T + ts) * 256 + blockIdx.x * 8 + 2 * tig;
        float mean = acc[0][0][rh * 2]     + pp[0] + bms;
        float lv   = acc[0][0][rh * 2 + 1] + pp[1] + bvs;
        float sd = __expf(0.5f * fminf(fmaxf(lv, -80.f), 80.f));
        float nz = noise[((size_t)b * T + ts) * S + s];
        g_z[(size_t)(ts + 1) * B * S + b * S + s] = t32(nz * sd + mean);
        kl += sd * sd + mean * mean - 0.5f * lv - 0.5f;
    }
    #pragma unroll
    for (int o = 16; o; o >>= 1) kl += __shfl_down_sync(0xffffffffu, kl, o);
    if (t == 0) klw[w] = (double)kl;
    __syncthreads();
    if (tid == 0) {
        double ssum = 0.0;
        #pragma unroll
        for (int i = 0; i < 8; i++) ssum += klw[i];
        g_klpart[(size_t)ts * 32 + blockIdx.x] = ssum;
    }
}

// ======================= postx: P = Xr @ Wmv[:, :512]^T  (all t at once) =======================
__global__ __launch_bounds__(256) void postx_k() {
    const int nb = blockIdx.x * 64, rb = blockIdx.y * 128;
    float acc[2][4][4];
    gemm_main<64, 4, 2, 2, 4>(acc, g_xr + (size_t)rb * DIN, DIN, 1 << 28,
                              g_xr, DIN, g_Wmv + (size_t)nb * 1536, 1536, 16);
    const int tid = threadIdx.x, t = tid & 31, w = tid >> 5;
    const int wm = w & 3, wn = w >> 2;
    #pragma unroll
    for (int mt = 0; mt < 2; mt++)
        #pragma unroll
        for (int nt = 0; nt < 4; nt++)
            #pragma unroll
            for (int rh = 0; rh < 2; rh++) {
                int row = rb + wm * 32 + mt * 16 + (t >> 2) + rh * 8;
                int col = nb + wn * 32 + nt * 8 + 2 * (t & 3);
                *(float2*)&g_P[(size_t)row * 256 + col] =
                    make_float2(acc[mt][nt][rh * 2], acc[mt][nt][rh * 2 + 1]);
            }
}

// ======================= decoder =======================
__global__ __launch_bounds__(256) void dec1_k(const float* __restrict__ bd1) {
    const int nb = blockIdx.x * 64, rb = blockIdx.y * 128;
    float acc[2][4][4];
    gemm_main<64, 4, 2, 2, 4>(acc, g_z + B * S + (size_t)rb * S, S, 1 << 28,
                              g_z, S, g_Wd1r + (size_t)nb * S, S, 4);
    const int tid = threadIdx.x, t = tid & 31, w = tid >> 5;
    const int wm = w & 3, wn = w >> 2;
    #pragma unroll
    for (int mt = 0; mt < 2; mt++)
        #pragma unroll
        for (int nt = 0; nt < 4; nt++)
            #pragma unroll
            for (int rh = 0; rh < 2; rh++) {
                int row = rb + wm * 32 + mt * 16 + (t >> 2) + rh * 8;
                int col = nb + wn * 32 + nt * 8 + 2 * (t & 3);
                float v0 = fmaxf(acc[mt][nt][rh * 2]     + bd1[col],     0.f);
                float v1 = fmaxf(acc[mt][nt][rh * 2 + 1] + bd1[col + 1], 0.f);
                *(float2*)&g_hid[(size_t)row * DH + col] = make_float2(t32(v0), t32(v1));
            }
}

__global__ __launch_bounds__(256) void dec2_k(const float* __restrict__ bd2,
                                              float* __restrict__ out) {
    const int nb = blockIdx.x * 64, rb = blockIdx.y * 128;
    float acc[2][4][4];
    gemm_main<64, 4, 2, 2, 4>(acc, g_hid + (size_t)rb * DH, DH, 1 << 28,
                              g_hid, DH, g_Wd2r + (size_t)nb * DH, DH, 32);
    const int tid = threadIdx.x, t = tid & 31, w = tid >> 5;
    const int wm = w & 3, wn = w >> 2;
    #pragma unroll
    for (int mt = 0; mt < 2; mt++)
        #pragma unroll
        for (int nt = 0; nt < 4; nt++)
            #pragma unroll
            for (int rh = 0; rh < 2; rh++) {
                int row = rb + wm * 32 + mt * 16 + (t >> 2) + rh * 8;   // row = t*128+b
                int col = nb + wn * 32 + nt * 8 + 2 * (t & 3);
                int tt = row >> 7, bb = row & 127;
                float v0 = acc[mt][nt][rh * 2]     + bd2[col];
                float v1 = acc[mt][nt][rh * 2 + 1] + bd2[col + 1];
                *(float2*)&out[((size_t)bb * T + tt) * DIN + col] = make_float2(v0, v1);
            }
}

// ======================= final KL reduce =======================
__global__ void kl_kernel(float* __restrict__ out) {
    __shared__ double red[256];
    int tid = threadIdx.x;
    double ssum = 0.0;
    for (int i = tid; i < T * 32; i += 256) ssum += g_klpart[i];
    red[tid] = ssum;
    __syncthreads();
    for (int off = 128; off; off >>= 1) {
        if (tid < off) red[tid] += red[tid + off];
        __syncthreads();
    }
    if (tid == 0) out[(size_t)B * T * DIN] = (float)red[0];
}

// ======================= host =======================
extern "C" void kernel_launch(void* const* d_in, const int* in_sizes, int n_in,
                              void* d_out, int out_size)
{
    const float* x     = (const float*)d_in[0];
    const float* noise = (const float*)d_in[1];
    const float* Wih   = (const float*)d_in[2];
    const float* Whh   = (const float*)d_in[3];
    const float* bih   = (const float*)d_in[4];
    const float* bhh   = (const float*)d_in[5];
    const float* Wm    = (const float*)d_in[6];
    const float* bm    = (const float*)d_in[7];
    const float* Wv    = (const float*)d_in[8];
    const float* bv    = (const float*)d_in[9];
    const float* Wd1   = (const float*)d_in[10];
    const float* bd1   = (const float*)d_in[11];
    const float* Wd2   = (const float*)d_in[12];
    const float* bd2   = (const float*)d_in[13];
    float* out = (float*)d_out;

    const int SM_A = 2 * 128 * 36 * 4;                 // 36864
    const int SMEM_LSTM = SM_A + 2 * 32 * 36 * 4;      // 46080
    const int SMEM_POST = SM_A + 2 * 8 * 36 * 4;       // 39168
    const int SMEM_DEC  = SM_A + 2 * 64 * 36 * 4;      // 55296
    cudaFuncSetAttribute(lstm_k,  cudaFuncAttributeMaxDynamicSharedMemorySize, SMEM_LSTM);
    cudaFuncSetAttribute(post_k,  cudaFuncAttributeMaxDynamicSharedMemorySize, SMEM_POST);
    cudaFuncSetAttribute(postx_k, cudaFuncAttributeMaxDynamicSharedMemorySize, SMEM_DEC);
    cudaFuncSetAttribute(dec1_k,  cudaFuncAttributeMaxDynamicSharedMemorySize, SMEM_DEC);
    cudaFuncSetAttribute(dec2_k,  cudaFuncAttributeMaxDynamicSharedMemorySize, SMEM_DEC);

    float *p_z, *p_h;
    cudaGetSymbolAddress((void**)&p_z, g_z);
    cudaGetSymbolAddress((void**)&p_h, g_h);

    init_kernel<<<256, 256>>>();
    prepack_kernel<<<1024, 256>>>(x, Wih, Whh, bih, bhh, Wm, Wv, Wd1, Wd2);
    postx_k<<<dim3(4, 256), 256, SMEM_DEC>>>();

    for (int t = 0; t < T; t++) {
        float* hin  = p_h + (size_t)(t & 1) * B * H;
        float* hout = p_h + (size_t)((t + 1) & 1) * B * H;
        lstm_k<<<128, 256, SMEM_LSTM>>>(p_z + (size_t)t * B * S, hin, hout);
        post_k<<<32, 256, SMEM_POST>>>(noise, bm, bv, hout, t);
    }
    dec1_k<<<dim3(16, 256), 256, SMEM_DEC>>>(bd1);
    dec2_k<<<dim3(8, 256), 256, SMEM_DEC>>>(bd2, out);
    kl_kernel<<<1, 256>>>(out);
}

// round 5
// speedup vs baseline: 3.0321x; 1.0390x over previous
#include <cuda_runtime.h>
#include <cstdint>

#define B   128
#define T   256
#define DIN 512
#define H   1024
#define S   128
#define DH  1024

// ---- scratch (device globals; no allocations allowed) ----
__device__ float  g_h[2][B * H];                 // hidden (tf32-rounded)
__device__ float  g_c[B * H];                    // cell (fp32)
__device__ float  g_z[(T + 1) * B * S];          // z slots (tf32-rounded); slot0 = zeros
__device__ float  g_hid[(size_t)B * T * DH];     // decoder mid (tf32-rounded)
__device__ float  g_P[(size_t)B * T * 256];      // precomputed x-part of posterior (fp32)
__device__ float  g_xr[(size_t)B * T * DIN];     // x rounded to tf32
__device__ float  g_Wp[4096 * 1152];             // gate-interleaved LSTM W (tf32)
__device__ float  g_bp[4096];                    // bih+bhh gate-interleaved (fp32)
__device__ float  g_Wmv[256 * 1536];             // rows 2s=Wm[s],2s+1=Wv[s] (tf32)
__device__ float  g_Wd1r[DH * S];                // tf32
__device__ float  g_Wd2r[DIN * DH];              // tf32
__device__ double g_klpart[T * 32];

// ======================= helpers =======================
__device__ __forceinline__ uint32_t smem_u32(const void* p) {
    uint32_t a;
    asm("{ .reg .u64 t; cvta.to.shared.u64 t, %1; cvt.u32.u64 %0, t; }" : "=r"(a) : "l"(p));
    return a;
}
__device__ __forceinline__ float t32(float x) {
    float r; asm("cvt.rna.tf32.f32 %0, %1;" : "=f"(r) : "f"(x)); return r;
}
__device__ __forceinline__ void cpa(uint32_t dst, const void* src) {
    asm volatile("cp.async.cg.shared.global [%0], [%1], 16;" :: "r"(dst), "l"(src) : "memory");
}
#define CP_COMMIT() asm volatile("cp.async.commit_group;" ::: "memory")
#define CP_WAITN(n) asm volatile("cp.async.wait_group %0;" :: "n"(n) : "memory")

__device__ __forceinline__ void ldsm4(uint32_t (&r)[4], uint32_t a) {
    asm volatile("ldmatrix.sync.aligned.m8n8.x4.shared.b16 {%0,%1,%2,%3}, [%4];"
                 : "=r"(r[0]), "=r"(r[1]), "=r"(r[2]), "=r"(r[3]) : "r"(a));
}
__device__ __forceinline__ void ldsm2(uint32_t (&r)[2], uint32_t a) {
    asm volatile("ldmatrix.sync.aligned.m8n8.x2.shared.b16 {%0,%1}, [%2];"
                 : "=r"(r[0]), "=r"(r[1]) : "r"(a));
}
__device__ __forceinline__ void mma8(float (&d)[4], const uint32_t (&a)[4], const uint32_t* b) {
    asm volatile("mma.sync.aligned.m16n8k8.row.col.f32.tf32.tf32.f32 "
        "{%0,%1,%2,%3}, {%4,%5,%6,%7}, {%8,%9}, {%0,%1,%2,%3};"
        : "+f"(d[0]), "+f"(d[1]), "+f"(d[2]), "+f"(d[3])
        : "r"(a[0]), "r"(a[1]), "r"(a[2]), "r"(a[3]), "r"(b[0]), "r"(b[1]));
}
__device__ __forceinline__ float fsig(float x) {
    float xc = fminf(fmaxf(x, -30.f), 30.f);
    return __fdividef(1.f, 1.f + __expf(-xc));
}
__device__ __forceinline__ float ftanh(float x) {
    float xc = fminf(fmaxf(x, -15.f), 15.f);
    float e = __expf(-2.f * xc);
    return __fdividef(1.f - e, 1.f + e);
}

// ======================= tf32 GEMM mainloop (4-stage cp.async ring) =======================
// C[128, NT] += A[128, 32*nchunks] @ W[NT, 32*nchunks]^T.  8 warps = NWM x NWN.
// A rows from a0 (chunks < split, stride sa0) then a1 (stride sa1). Pitch 36 floats.
// One __syncthreads per chunk:  wait(c) -> sync -> issue(c+NS-1) [buf (c-1)%NS, proven free
// by the sync] -> compute(c).
template<int NT, int NWM, int NWN, int MT, int NTT>
__device__ __forceinline__ void gemm_main(
    float (&acc)[MT][NTT][4],
    const float* a0, int sa0, int split, const float* a1, int sa1,
    const float* wsrc, int sw, int nchunks)
{
    constexpr int NS = 4;
    extern __shared__ float smem[];
    float* As = smem;                       // [NS][128*36]
    float* Ws = smem + NS * 128 * 36;       // [NS][NT*36]
    const int tid = threadIdx.x;
    const int t = tid & 31, w = tid >> 5;
    const int wm = w % NWM, wn = w / NWM;
    const int m0 = wm * (128 / NWM), n0 = wn * (NT / NWN);

    #pragma unroll
    for (int mt = 0; mt < MT; mt++)
        #pragma unroll
        for (int nt = 0; nt < NTT; nt++)
            #pragma unroll
            for (int q = 0; q < 4; q++) acc[mt][nt][q] = 0.f;

    const uint32_t as_b = smem_u32(As), ws_b = smem_u32(Ws);

    // ldmatrix per-thread byte offsets (within a buffer, before +j*32)
    uint32_t aoff[MT];
    #pragma unroll
    for (int mt = 0; mt < MT; mt++) {
        int row = m0 + mt * 16 + (t & 7) + ((t >> 3) & 1) * 8;
        aoff[mt] = (uint32_t)(row * 36 + (t >> 4) * 4) * 4u;
    }
    constexpr int NP = (NTT + 1) / 2;
    uint32_t woff[NP];
    if constexpr (NTT == 1) {
        int row = n0 + (t & 7);
        woff[0] = (uint32_t)(row * 36 + ((t >> 3) & 1) * 4) * 4u;
    } else {
        #pragma unroll
        for (int p = 0; p < NP; p++) {
            int row = n0 + p * 16 + (t & 7) + ((t >> 4) & 1) * 8;
            woff[p] = (uint32_t)(row * 36 + ((t >> 3) & 1) * 4) * 4u;
        }
    }

    constexpr int WU = NT * 8;               // 16B units in W chunk
    constexpr int WI = (WU + 255) / 256;

    auto issue = [&](int c) {
        int buf = c & (NS - 1);
        const float* ap; int sa;
        if (c < split) { ap = a0 + c * 32;           sa = sa0; }
        else           { ap = a1 + (c - split) * 32; sa = sa1; }
        uint32_t ad = as_b + (uint32_t)buf * (128 * 36 * 4);
        #pragma unroll
        for (int i = 0; i < 4; i++) {
            int u = tid + i * 256;
            int row = u >> 3, kc = (u & 7) * 4;
            cpa(ad + (uint32_t)(row * 36 + kc) * 4u, ap + (size_t)row * sa + kc);
        }
        const float* wp = wsrc + c * 32;
        uint32_t wd = ws_b + (uint32_t)buf * (NT * 36 * 4);
        #pragma unroll
        for (int i = 0; i < WI; i++) {
            int u = tid + i * 256;
            if ((WU % 256 == 0) || (u < WU)) {
                int row = u >> 3, kc = (u & 7) * 4;
                cpa(wd + (uint32_t)(row * 36 + kc) * 4u, wp + (size_t)row * sw + kc);
            }
        }
        CP_COMMIT();
    };

    // prologue: NS-1 chunks in flight (callers guarantee nchunks >= NS-1)
    issue(0); issue(1); issue(2);

    for (int c = 0; c < nchunks; c++) {
        int rem = nchunks - 1 - c;           // groups allowed to stay pending
        if (rem >= NS - 2)      { CP_WAITN(NS - 2); }
        else if (rem == 1)      { CP_WAITN(1); }
        else                    { CP_WAITN(0); }
        __syncthreads();
        if (c + NS - 1 < nchunks) issue(c + NS - 1);

        uint32_t ab = as_b + (uint32_t)(c & (NS - 1)) * (128 * 36 * 4);
        uint32_t wb = ws_b + (uint32_t)(c & (NS - 1)) * (NT * 36 * 4);
        #pragma unroll
        for (int j = 0; j < 4; j++) {
            uint32_t afr[MT][4];
            #pragma unroll
            for (int mt = 0; mt < MT; mt++) ldsm4(afr[mt], ab + aoff[mt] + j * 32);
            uint32_t bfr[NTT][2];
            if constexpr (NTT == 1) {
                uint32_t r2[2];
                ldsm2(r2, wb + woff[0] + j * 32);
                bfr[0][0] = r2[0]; bfr[0][1] = r2[1];
            } else {
                #pragma unroll
                for (int p = 0; p < NP; p++) {
                    uint32_t r4[4];
                    ldsm4(r4, wb + woff[p] + j * 32);
                    bfr[2 * p][0] = r4[0]; bfr[2 * p][1] = r4[1];
                    bfr[2 * p + 1][0] = r4[2]; bfr[2 * p + 1][1] = r4[3];
                }
            }
            #pragma unroll
            for (int mt = 0; mt < MT; mt++)
                #pragma unroll
                for (int nt = 0; nt < NTT; nt++)
                    mma8(acc[mt][nt], afr[mt], bfr[nt]);
        }
    }
    __syncthreads();
}

// ======================= init / prepack =======================
__global__ void init_kernel() {
    int stride = gridDim.x * blockDim.x;
    int t0 = blockIdx.x * blockDim.x + threadIdx.x;
    for (int i = t0; i < B * H; i += stride) { g_h[0][i] = 0.f; g_c[i] = 0.f; }
    for (int i = t0; i < B * S; i += stride) g_z[i] = 0.f;
}

__global__ void prepack_kernel(
    const float* __restrict__ x,
    const float* __restrict__ Wih, const float* __restrict__ Whh,
    const float* __restrict__ bih, const float* __restrict__ bhh,
    const float* __restrict__ Wm, const float* __restrict__ Wv,
    const float* __restrict__ Wd1, const float* __restrict__ Wd2)
{
    size_t stride = (size_t)gridDim.x * blockDim.x;
    size_t t0 = (size_t)blockIdx.x * blockDim.x + threadIdx.x;
    for (size_t i = t0; i < (size_t)4096 * 1152; i += stride) {
        int n = (int)(i / 1152), k = (int)(i % 1152);
        int j = n >> 2, g = n & 3;
        float v = (k < S) ? Wih[(size_t)(g * H + j) * S + k]
                          : Whh[(size_t)(g * H + j) * H + (k - S)];
        g_Wp[i] = t32(v);
    }
    for (size_t i = t0; i < (size_t)256 * 1536; i += stride) {
        int n = (int)(i / 1536), k = (int)(i % 1536);
        const float* src = (n & 1) ? Wv : Wm;
        g_Wmv[i] = t32(src[(size_t)(n >> 1) * 1536 + k]);
    }
    for (size_t i = t0; i < (size_t)DH * S; i += stride)   g_Wd1r[i] = t32(Wd1[i]);
    for (size_t i = t0; i < (size_t)DIN * DH; i += stride) g_Wd2r[i] = t32(Wd2[i]);
    for (size_t i = t0; i < (size_t)B * T * DIN; i += stride) g_xr[i] = t32(x[i]);
    for (size_t i = t0; i < 4096; i += stride) {
        int j = (int)(i >> 2), g = (int)(i & 3);
        g_bp[i] = bih[g * H + j] + bhh[g * H + j];
    }
}

// ======================= LSTM step: 128 CTAs x N32, fused pointwise =======================
__global__ __launch_bounds__(256) void lstm_k(
    const float* __restrict__ zt, const float* __restrict__ hin, float* __restrict__ hout)
{
    float acc[2][2][4];
    gemm_main<32, 4, 2, 2, 2>(acc, zt, S, 4, hin, H,
                              g_Wp + (size_t)blockIdx.x * 32 * 1152, 1152, 36);

    const int tid = threadIdx.x, t = tid & 31, w = tid >> 5;
    const int wm = w & 3, wn = w >> 2;
    const int m0 = wm * 32, n0 = wn * 16;
    const bool even = (t & 1) == 0;

    #pragma unroll
    for (int mt = 0; mt < 2; mt++)
        #pragma unroll
        for (int nt = 0; nt < 2; nt++)
            #pragma unroll
            for (int rh = 0; rh < 2; rh++) {
                float v0 = acc[mt][nt][rh * 2], v1 = acc[mt][nt][rh * 2 + 1];
                float p0 = __shfl_xor_sync(0xffffffffu, v0, 1);
                float p1 = __shfl_xor_sync(0xffffffffu, v1, 1);
                if (even) {
                    int lc = n0 + nt * 8 + 2 * (t & 3);        // multiple of 4
                    int pcb = blockIdx.x * 32 + lc;
                    int j = pcb >> 2;
                    float4 bb = *(const float4*)&g_bp[pcb];
                    int b = m0 + mt * 16 + (t >> 2) + rh * 8;
                    float cold = g_c[b * H + j];
                    float i_ = fsig(v0 + bb.x);
                    float f_ = fsig(v1 + bb.y);
                    float gg = ftanh(p0 + bb.z);
                    float o_ = fsig(p1 + bb.w);
                    float cn = f_ * cold + i_ * gg;
                    g_c[b * H + j] = cn;
                    hout[b * H + j] = t32(o_ * ftanh(cn));
                }
            }
}

// ======================= posterior step: 32 CTAs x N8 (h-part only) =======================
__global__ __launch_bounds__(256) void post_k(
    const float* __restrict__ noise,
    const float* __restrict__ bm, const float* __restrict__ bv,
    const float* __restrict__ hin, int ts)
{
    float acc[1][1][4];
    gemm_main<8, 8, 1, 1, 1>(acc, hin, H, 1 << 28, hin, H,
                             g_Wmv + (size_t)blockIdx.x * 8 * 1536 + 512, 1536, 32);

    __shared__ double klw[8];
    const int tid = threadIdx.x, t = tid & 31, w = tid >> 5;
    const int m0 = w * 16, tig = t & 3;
    const int s = blockIdx.x * 4 + tig;
    const float bms = bm[s], bvs = bv[s];
    float kl = 0.f;
    #pragma unroll
    for (int rh = 0; rh < 2; rh++) {
        int b = m0 + (t >> 2) + rh * 8;
        const float* pp = g_P + ((size_t)b * T + ts) * 256 + blockIdx.x * 8 + 2 * tig;
        float mean = acc[0][0][rh * 2]     + pp[0] + bms;
        float lv   = acc[0][0][rh * 2 + 1] + pp[1] + bvs;
        float sd = __expf(0.5f * fminf(fmaxf(lv, -80.f), 80.f));
        float nz = noise[((size_t)b * T + ts) * S + s];
        g_z[(size_t)(ts + 1) * B * S + b * S + s] = t32(nz * sd + mean);
        kl += sd * sd + mean * mean - 0.5f * lv - 0.5f;
    }
    #pragma unroll
    for (int o = 16; o; o >>= 1) kl += __shfl_down_sync(0xffffffffu, kl, o);
    if (t == 0) klw[w] = (double)kl;
    __syncthreads();
    if (tid == 0) {
        double ssum = 0.0;
        #pragma unroll
        for (int i = 0; i < 8; i++) ssum += klw[i];
        g_klpart[(size_t)ts * 32 + blockIdx.x] = ssum;
    }
}

// ======================= postx: P = Xr @ Wmv[:, :512]^T  (all t at once) =======================
__global__ __launch_bounds__(256) void postx_k() {
    const int nb = blockIdx.x * 64, rb = blockIdx.y * 128;
    float acc[2][4][4];
    gemm_main<64, 4, 2, 2, 4>(acc, g_xr + (size_t)rb * DIN, DIN, 1 << 28,
                              g_xr, DIN, g_Wmv + (size_t)nb * 1536, 1536, 16);
    const int tid = threadIdx.x, t = tid & 31, w = tid >> 5;
    const int wm = w & 3, wn = w >> 2;
    #pragma unroll
    for (int mt = 0; mt < 2; mt++)
        #pragma unroll
        for (int nt = 0; nt < 4; nt++)
            #pragma unroll
            for (int rh = 0; rh < 2; rh++) {
                int row = rb + wm * 32 + mt * 16 + (t >> 2) + rh * 8;
                int col = nb + wn * 32 + nt * 8 + 2 * (t & 3);
                *(float2*)&g_P[(size_t)row * 256 + col] =
                    make_float2(acc[mt][nt][rh * 2], acc[mt][nt][rh * 2 + 1]);
            }
}

// ======================= decoder =======================
__global__ __launch_bounds__(256) void dec1_k(const float* __restrict__ bd1) {
    const int nb = blockIdx.x * 64, rb = blockIdx.y * 128;
    float acc[2][4][4];
    gemm_main<64, 4, 2, 2, 4>(acc, g_z + B * S + (size_t)rb * S, S, 1 << 28,
                              g_z, S, g_Wd1r + (size_t)nb * S, S, 4);
    const int tid = threadIdx.x, t = tid & 31, w = tid >> 5;
    const int wm = w & 3, wn = w >> 2;
    #pragma unroll
    for (int mt = 0; mt < 2; mt++)
        #pragma unroll
        for (int nt = 0; nt < 4; nt++)
            #pragma unroll
            for (int rh = 0; rh < 2; rh++) {
                int row = rb + wm * 32 + mt * 16 + (t >> 2) + rh * 8;
                int col = nb + wn * 32 + nt * 8 + 2 * (t & 3);
                float v0 = fmaxf(acc[mt][nt][rh * 2]     + bd1[col],     0.f);
                float v1 = fmaxf(acc[mt][nt][rh * 2 + 1] + bd1[col + 1], 0.f);
                *(float2*)&g_hid[(size_t)row * DH + col] = make_float2(t32(v0), t32(v1));
            }
}

__global__ __launch_bounds__(256) void dec2_k(const float* __restrict__ bd2,
                                              float* __restrict__ out) {
    const int nb = blockIdx.x * 64, rb = blockIdx.y * 128;
    float acc[2][4][4];
    gemm_main<64, 4, 2, 2, 4>(acc, g_hid + (size_t)rb * DH, DH, 1 << 28,
                              g_hid, DH, g_Wd2r + (size_t)nb * DH, DH, 32);
    const int tid = threadIdx.x, t = tid & 31, w = tid >> 5;
    const int wm = w & 3, wn = w >> 2;
    #pragma unroll
    for (int mt = 0; mt < 2; mt++)
        #pragma unroll
        for (int nt = 0; nt < 4; nt++)
            #pragma unroll
            for (int rh = 0; rh < 2; rh++) {
                int row = rb + wm * 32 + mt * 16 + (t >> 2) + rh * 8;   // row = t*128+b
                int col = nb + wn * 32 + nt * 8 + 2 * (t & 3);
                int tt = row >> 7, bb = row & 127;
                float v0 = acc[mt][nt][rh * 2]     + bd2[col];
                float v1 = acc[mt][nt][rh * 2 + 1] + bd2[col + 1];
                *(float2*)&out[((size_t)bb * T + tt) * DIN + col] = make_float2(v0, v1);
            }
}

// ======================= final KL reduce =======================
__global__ void kl_kernel(float* __restrict__ out) {
    __shared__ double red[256];
    int tid = threadIdx.x;
    double ssum = 0.0;
    for (int i = tid; i < T * 32; i += 256) ssum += g_klpart[i];
    red[tid] = ssum;
    __syncthreads();
    for (int off = 128; off; off >>= 1) {
        if (tid < off) red[tid] += red[tid + off];
        __syncthreads();
    }
    if (tid == 0) out[(size_t)B * T * DIN] = (float)red[0];
}

// ======================= host =======================
extern "C" void kernel_launch(void* const* d_in, const int* in_sizes, int n_in,
                              void* d_out, int out_size)
{
    const float* x     = (const float*)d_in[0];
    const float* noise = (const float*)d_in[1];
    const float* Wih   = (const float*)d_in[2];
    const float* Whh   = (const float*)d_in[3];
    const float* bih   = (const float*)d_in[4];
    const float* bhh   = (const float*)d_in[5];
    const float* Wm    = (const float*)d_in[6];
    const float* bm    = (const float*)d_in[7];
    const float* Wv    = (const float*)d_in[8];
    const float* bv    = (const float*)d_in[9];
    const float* Wd1   = (const float*)d_in[10];
    const float* bd1   = (const float*)d_in[11];
    const float* Wd2   = (const float*)d_in[12];
    const float* bd2   = (const float*)d_in[13];
    float* out = (float*)d_out;

    const int SM_A = 4 * 128 * 36 * 4;                 // 73728
    const int SMEM_LSTM = SM_A + 4 * 32 * 36 * 4;      //  92160
    const int SMEM_POST = SM_A + 4 * 8 * 36 * 4;       //  78336
    const int SMEM_DEC  = SM_A + 4 * 64 * 36 * 4;      // 110592
    cudaFuncSetAttribute(lstm_k,  cudaFuncAttributeMaxDynamicSharedMemorySize, SMEM_LSTM);
    cudaFuncSetAttribute(post_k,  cudaFuncAttributeMaxDynamicSharedMemorySize, SMEM_POST);
    cudaFuncSetAttribute(postx_k, cudaFuncAttributeMaxDynamicSharedMemorySize, SMEM_DEC);
    cudaFuncSetAttribute(dec1_k,  cudaFuncAttributeMaxDynamicSharedMemorySize, SMEM_DEC);
    cudaFuncSetAttribute(dec2_k,  cudaFuncAttributeMaxDynamicSharedMemorySize, SMEM_DEC);

    float *p_z, *p_h;
    cudaGetSymbolAddress((void**)&p_z, g_z);
    cudaGetSymbolAddress((void**)&p_h, g_h);

    init_kernel<<<256, 256>>>();
    prepack_kernel<<<1024, 256>>>(x, Wih, Whh, bih, bhh, Wm, Wv, Wd1, Wd2);
    postx_k<<<dim3(4, 256), 256, SMEM_DEC>>>();

    for (int t = 0; t < T; t++) {
        float* hin  = p_h + (size_t)(t & 1) * B * H;
        float* hout = p_h + (size_t)((t + 1) & 1) * B * H;
        lstm_k<<<128, 256, SMEM_LSTM>>>(p_z + (size_t)t * B * S, hin, hout);
        post_k<<<32, 256, SMEM_POST>>>(noise, bm, bv, hout, t);
    }
    dec1_k<<<dim3(16, 256), 256, SMEM_DEC>>>(bd1);
    dec2_k<<<dim3(8, 256), 256, SMEM_DEC>>>(bd2, out);
    kl_kernel<<<1, 256>>>(out);
}

// round 6
// speedup vs baseline: 3.5313x; 1.1647x over previous
#include <cuda_runtime.h>
#include <cstdint>

#define B   128
#define T   256
#define DIN 512
#define H   1024
#define S   128
#define DH  1024

// ---- scratch (device globals; image layout = pre-swizzled 128B-row tiles) ----
__device__ float  g_h[2][B * H];                  // hidden, image layout [32 chunks][128x32]
__device__ float  g_c[B * H];                     // cell, linear
__device__ float  g_z[(T + 1) * B * S];           // z slots, each [4 chunks][128x32]
__device__ float  g_hid[(size_t)B * T * DH];      // [256 rowtiles][32 chunks][128x32]
__device__ float  g_P[(size_t)B * T * 256];       // x-part of posterior, linear
__device__ float  g_xri[(size_t)B * T * DIN];     // x images [256 rt][16 c][128x32]
__device__ float  g_Wp[64 * 36 * 2048];           // lstm W [64 ntiles][36 c][64x32]
__device__ float  g_bp[4096];                     // bih+bhh gate-interleaved
__device__ float  g_Wmvh[32 * 32 * 256];          // post W (h-part) [32 nt][32 c][8x32]
__device__ float  g_Wmvx[4 * 16 * 2048];          // postx W [4 nt][16 c][64x32]
__device__ float  g_Wd1i[16 * 4 * 2048];          // [16 nt][4 c][64x32]
__device__ float  g_Wd2i[8 * 32 * 2048];          // [8 nt][32 c][64x32]
__device__ double g_klpart[T * 32];

// ======================= helpers =======================
__device__ __forceinline__ uint32_t smem_u32(const void* p) {
    uint32_t a;
    asm("{ .reg .u64 t; cvta.to.shared.u64 t, %1; cvt.u32.u64 %0, t; }" : "=r"(a) : "l"(p));
    return a;
}
__device__ __forceinline__ float t32(float x) {
    float r; asm("cvt.rna.tf32.f32 %0, %1;" : "=f"(r) : "f"(x)); return r;
}
// swizzled offset (floats) of (row, k) inside a [rows x 32] tile image
__device__ __forceinline__ int imgoff(int row, int k) {
    return row * 32 + ((((k >> 2) ^ row) & 7) << 2) + (k & 3);
}

#define MBAR_INIT(a, c) \
    asm volatile("mbarrier.init.shared.b64 [%0], %1;" :: "r"(a), "r"(c) : "memory")

#define MBAR_WAIT(a, ph) do {                                                   \
    uint32_t _m = (a), _p = (uint32_t)(ph), _d;                                 \
    asm volatile("{\n\t.reg .pred p;\n\t"                                       \
        "mbarrier.try_wait.parity.acquire.cta.shared::cta.b64 p, [%1], %2;\n\t" \
        "selp.b32 %0, 1, 0, p;\n\t}"                                            \
        : "=r"(_d) : "r"(_m), "r"(_p) : "memory");                              \
    if (!_d) {                                                                  \
        asm volatile("{\n\t.reg .pred P1;\n\t"                                  \
        "WL%=:\n\t"                                                             \
        "mbarrier.try_wait.parity.acquire.cta.shared::cta.b64 P1, [%0], %1, 0x989680;\n\t" \
        "@P1 bra.uni WD%=;\n\t"                                                 \
        "bra.uni WL%=;\n\t"                                                     \
        "WD%=:\n\t}"                                                            \
        :: "r"(_m), "r"(_p) : "memory");                                        \
    } } while (0)

#define EXPECT_TX(mb, n) \
    asm volatile("mbarrier.arrive.expect_tx.shared.b64 _, [%0], %1;" \
                 :: "r"(mb), "r"((uint32_t)(n)) : "memory")
#define BULK_G2S(dst, src, n, mb) \
    asm volatile("cp.async.bulk.shared::cluster.global.mbarrier::complete_tx::bytes " \
                 "[%0], [%1], %2, [%3];" \
                 :: "r"(dst), "l"(src), "r"((uint32_t)(n)), "r"(mb) : "memory")

__device__ __forceinline__ void ldsm4(uint32_t (&r)[4], uint32_t a) {
    asm volatile("ldmatrix.sync.aligned.m8n8.x4.shared.b16 {%0,%1,%2,%3}, [%4];"
                 : "=r"(r[0]), "=r"(r[1]), "=r"(r[2]), "=r"(r[3]) : "r"(a));
}
__device__ __forceinline__ void ldsm2(uint32_t (&r)[2], uint32_t a) {
    asm volatile("ldmatrix.sync.aligned.m8n8.x2.shared.b16 {%0,%1}, [%2];"
                 : "=r"(r[0]), "=r"(r[1]) : "r"(a));
}
__device__ __forceinline__ void mma8(float (&d)[4], const uint32_t (&a)[4], const uint32_t* b) {
    asm volatile("mma.sync.aligned.m16n8k8.row.col.f32.tf32.tf32.f32 "
        "{%0,%1,%2,%3}, {%4,%5,%6,%7}, {%8,%9}, {%0,%1,%2,%3};"
        : "+f"(d[0]), "+f"(d[1]), "+f"(d[2]), "+f"(d[3])
        : "r"(a[0]), "r"(a[1]), "r"(a[2]), "r"(a[3]), "r"(b[0]), "r"(b[1]));
}
__device__ __forceinline__ float fsig(float x) {
    float xc = fminf(fmaxf(x, -30.f), 30.f);
    return __fdividef(1.f, 1.f + __expf(-xc));
}
__device__ __forceinline__ float ftanh(float x) {
    float xc = fminf(fmaxf(x, -15.f), 15.f);
    float e = __expf(-2.f * xc);
    return __fdividef(1.f - e, 1.f + e);
}

// ======================= bulk-DMA tf32 GEMM mainloop =======================
// C[128, NT] += A[128, K] @ W[NT, K]^T, K = 32*KI*nchunks, operands in pre-swizzled
// image format. One chunk = KI A-images (16KB each) + KI W-images (NT*128B each),
// loaded with 2 bulk copies by thread 0 into an NS-stage ring paced by mbarriers.
// A images: chunk < split from a0, rest from a1 (both contiguous image sequences).
template<int NT, int NWM, int NWN, int MT, int NTT, int KI, int NS>
__device__ __forceinline__ void gemm_bulk(
    float (&acc)[MT][NTT][4],
    const float* a0, int split, const float* a1,
    const float* wsrc, int nchunks)
{
    extern __shared__ char smem[];
    constexpr uint32_t AB  = (uint32_t)KI * 16384u;
    constexpr uint32_t WB  = (uint32_t)KI * NT * 128u;
    constexpr uint32_t STG = AB + WB;
    const int tid = threadIdx.x;
    const int t = tid & 31, w = tid >> 5;
    const int wm = w % NWM, wn = w / NWM;
    const int m0 = wm * (128 / NWM), n0 = wn * (NT / NWN);
    const uint32_t ctrl = smem_u32(smem);
    const uint32_t base = ctrl + 128;

    #pragma unroll
    for (int mt = 0; mt < MT; mt++)
        #pragma unroll
        for (int nt = 0; nt < NTT; nt++)
            #pragma unroll
            for (int q = 0; q < 4; q++) acc[mt][nt][q] = 0.f;

    int arowb[MT], arx[MT];
    #pragma unroll
    for (int mt = 0; mt < MT; mt++) {
        int r = m0 + mt * 16 + (t & 7) + ((t >> 3) & 1) * 8;
        arowb[mt] = r * 128; arx[mt] = r & 7;
    }
    const int au0 = (t >> 4) & 1;
    constexpr int NP = (NTT + 1) / 2;
    int wrowb[NP], wrx[NP], wu0;
    if constexpr (NTT == 1) {
        int r = n0 + (t & 7);
        wrowb[0] = r * 128; wrx[0] = r & 7; wu0 = (t >> 3) & 1;
    } else {
        #pragma unroll
        for (int p = 0; p < NP; p++) {
            int r = n0 + p * 16 + (t & 7) + ((t >> 4) & 1) * 8;
            wrowb[p] = r * 128; wrx[p] = r & 7;
        }
        wu0 = (t >> 3) & 1;
    }

    if (tid == 0) {
        #pragma unroll
        for (int s = 0; s < NS; s++) MBAR_INIT(ctrl + s * 8, 1);
    }
    __syncthreads();

    auto issue = [&](int c) {
        uint32_t mb = ctrl + (uint32_t)(c % NS) * 8;
        uint32_t ab = base + (uint32_t)(c % NS) * STG;
        EXPECT_TX(mb, AB + WB);
        const float* ap = (c < split) ? a0 + (size_t)c * (KI * 4096)
                                      : a1 + (size_t)(c - split) * (KI * 4096);
        BULK_G2S(ab, ap, AB, mb);
        BULK_G2S(ab + AB, wsrc + (size_t)c * (KI * NT * 32), WB, mb);
    };
    if (tid == 0)
        for (int i = 0; i < NS - 1 && i < nchunks; i++) issue(i);

    for (int c = 0; c < nchunks; c++) {
        __syncthreads();                       // all threads done with chunk c-1
        if (tid == 0 && c + NS - 1 < nchunks) issue(c + NS - 1);
        int st = c % NS, ph = (c / NS) & 1;
        MBAR_WAIT(ctrl + (uint32_t)st * 8, ph);
        uint32_t ab = base + (uint32_t)st * STG, wb = ab + AB;
        #pragma unroll
        for (int jj = 0; jj < 4 * KI; jj++) {
            const int img = jj >> 2, j = jj & 3;
            const uint32_t abj = ab + img * 16384;
            const uint32_t wbj = wb + img * (NT * 128);
            uint32_t afr[MT][4];
            #pragma unroll
            for (int mt = 0; mt < MT; mt++)
                ldsm4(afr[mt], abj + arowb[mt] + (((2 * j + au0) ^ arx[mt]) << 4));
            uint32_t bfr[NTT][2];
            if constexpr (NTT == 1) {
                uint32_t r2[2];
                ldsm2(r2, wbj + wrowb[0] + (((2 * j + wu0) ^ wrx[0]) << 4));
                bfr[0][0] = r2[0]; bfr[0][1] = r2[1];
            } else {
                #pragma unroll
                for (int p = 0; p < NP; p++) {
                    uint32_t r4[4];
                    ldsm4(r4, wbj + wrowb[p] + (((2 * j + wu0) ^ wrx[p]) << 4));
                    bfr[2 * p][0] = r4[0]; bfr[2 * p][1] = r4[1];
                    bfr[2 * p + 1][0] = r4[2]; bfr[2 * p + 1][1] = r4[3];
                }
            }
            #pragma unroll
            for (int mt = 0; mt < MT; mt++)
                #pragma unroll
                for (int nt = 0; nt < NTT; nt++)
                    mma8(acc[mt][nt], afr[mt], bfr[nt]);
        }
    }
}

// ======================= init / prepack =======================
__global__ void init_kernel() {
    int stride = gridDim.x * blockDim.x;
    int t0 = blockIdx.x * blockDim.x + threadIdx.x;
    for (int i = t0; i < B * H; i += stride) { g_h[0][i] = 0.f; g_c[i] = 0.f; }
    for (int i = t0; i < B * S; i += stride) g_z[i] = 0.f;
}

__global__ void prepack_kernel(
    const float* __restrict__ x,
    const float* __restrict__ Wih, const float* __restrict__ Whh,
    const float* __restrict__ bih, const float* __restrict__ bhh,
    const float* __restrict__ Wm, const float* __restrict__ Wv,
    const float* __restrict__ Wd1, const float* __restrict__ Wd2)
{
    size_t stride = (size_t)gridDim.x * blockDim.x;
    size_t t0 = (size_t)blockIdx.x * blockDim.x + threadIdx.x;
    // lstm W: [64 nt][36 c][64x32]
    for (size_t i = t0; i < (size_t)64 * 36 * 2048; i += stride) {
        int k = (int)(i & 31), r = (int)((i >> 5) & 63);
        size_t tc = i >> 11;                       // n*36 + c
        int c = (int)(tc % 36), n = (int)(tc / 36);
        int gc = n * 64 + r, j = gc >> 2, g = gc & 3, kc = c * 32 + k;
        float v = (kc < S) ? Wih[(size_t)(g * H + j) * S + kc]
                           : Whh[(size_t)(g * H + j) * H + (kc - S)];
        g_Wp[(tc << 11) + imgoff(r, k)] = t32(v);
    }
    // post W (h cols): [32 nt][32 c][8x32]
    for (size_t i = t0; i < (size_t)32 * 32 * 256; i += stride) {
        int k = (int)(i & 31), r = (int)((i >> 5) & 7);
        size_t tc = i >> 8;
        int c = (int)(tc & 31), nt = (int)(tc >> 5);
        int n = nt * 8 + r, col = 512 + c * 32 + k;
        const float* src = (n & 1) ? Wv : Wm;
        g_Wmvh[(tc << 8) + imgoff(r, k)] = t32(src[(size_t)(n >> 1) * 1536 + col]);
    }
    // postx W (x cols): [4 nt][16 c][64x32]
    for (size_t i = t0; i < (size_t)4 * 16 * 2048; i += stride) {
        int k = (int)(i & 31), r = (int)((i >> 5) & 63);
        size_t tc = i >> 11;
        int c = (int)(tc & 15), nt = (int)(tc >> 4);
        int n = nt * 64 + r, col = c * 32 + k;
        const float* src = (n & 1) ? Wv : Wm;
        g_Wmvx[(tc << 11) + imgoff(r, k)] = t32(src[(size_t)(n >> 1) * 1536 + col]);
    }
    // Wd1: [16 nt][4 c][64x32]
    for (size_t i = t0; i < (size_t)16 * 4 * 2048; i += stride) {
        int k = (int)(i & 31), r = (int)((i >> 5) & 63);
        size_t tc = i >> 11;
        int c = (int)(tc & 3), nt = (int)(tc >> 2);
        g_Wd1i[(tc << 11) + imgoff(r, k)] =
            t32(Wd1[(size_t)(nt * 64 + r) * S + c * 32 + k]);
    }
    // Wd2: [8 nt][32 c][64x32]
    for (size_t i = t0; i < (size_t)8 * 32 * 2048; i += stride) {
        int k = (int)(i & 31), r = (int)((i >> 5) & 63);
        size_t tc = i >> 11;
        int c = (int)(tc & 31), nt = (int)(tc >> 5);
        g_Wd2i[(tc << 11) + imgoff(r, k)] =
            t32(Wd2[(size_t)(nt * 64 + r) * DH + c * 32 + k]);
    }
    // x images: [256 rt][16 c][128x32], row = b*T + t
    for (size_t i = t0; i < (size_t)256 * 16 * 4096; i += stride) {
        int k = (int)(i & 31), r = (int)((i >> 5) & 127);
        size_t tc = i >> 12;
        int c = (int)(tc & 15), rt = (int)(tc >> 4);
        size_t row = (size_t)rt * 128 + r;
        g_xri[(tc << 12) + imgoff(r, k)] = t32(x[row * DIN + c * 32 + k]);
    }
    for (size_t i = t0; i < 4096; i += stride) {
        int j = (int)(i >> 2), g = (int)(i & 3);
        g_bp[i] = bih[g * H + j] + bhh[g * H + j];
    }
}

// ======================= LSTM step: 64 CTAs x N64, fused pointwise =======================
__global__ __launch_bounds__(256) void lstm_k(
    const float* __restrict__ zt, const float* __restrict__ hin, float* __restrict__ hout)
{
    float acc[2][4][4];
    gemm_bulk<64, 4, 2, 2, 4, 2, 3>(acc, zt, 2, hin,
                                    g_Wp + (size_t)blockIdx.x * 36 * 2048, 18);

    const int tid = threadIdx.x, t = tid & 31, w = tid >> 5;
    const int wm = w & 3, wn = w >> 2;
    const int m0 = wm * 32, n0 = wn * 32;
    const bool even = (t & 1) == 0;

    #pragma unroll
    for (int mt = 0; mt < 2; mt++)
        #pragma unroll
        for (int nt = 0; nt < 4; nt++)
            #pragma unroll
            for (int rh = 0; rh < 2; rh++) {
                float v0 = acc[mt][nt][rh * 2], v1 = acc[mt][nt][rh * 2 + 1];
                float p0 = __shfl_xor_sync(0xffffffffu, v0, 1);
                float p1 = __shfl_xor_sync(0xffffffffu, v1, 1);
                if (even) {
                    int lc = n0 + nt * 8 + 2 * (t & 3);
                    int pcb = blockIdx.x * 64 + lc;        // gate-interleaved col
                    int j = pcb >> 2;
                    float4 bb = *(const float4*)&g_bp[pcb];
                    int b = m0 + mt * 16 + (t >> 2) + rh * 8;
                    float cold = g_c[b * H + j];
                    float i_ = fsig(v0 + bb.x);
                    float f_ = fsig(v1 + bb.y);
                    float gg = ftanh(p0 + bb.z);
                    float o_ = fsig(p1 + bb.w);
                    float cn = f_ * cold + i_ * gg;
                    g_c[b * H + j] = cn;
                    hout[(j >> 5) * 4096 + imgoff(b, j & 31)] = t32(o_ * ftanh(cn));
                }
            }
}

// ======================= posterior step: 32 CTAs x N8 (h-part) =======================
__global__ __launch_bounds__(256) void post_k(
    const float* __restrict__ noise,
    const float* __restrict__ bm, const float* __restrict__ bv,
    const float* __restrict__ hin, int ts)
{
    float acc[1][1][4];
    gemm_bulk<8, 8, 1, 1, 1, 2, 3>(acc, hin, 1 << 28, hin,
                                   g_Wmvh + (size_t)blockIdx.x * 32 * 256, 16);

    __shared__ double klw[8];
    const int tid = threadIdx.x, t = tid & 31, w = tid >> 5;
    const int m0 = w * 16, tig = t & 3;
    const int s = blockIdx.x * 4 + tig;
    const float bms = bm[s], bvs = bv[s];
    float kl = 0.f;
    #pragma unroll
    for (int rh = 0; rh < 2; rh++) {
        int b = m0 + (t >> 2) + rh * 8;
        const float* pp = g_P + ((size_t)b * T + ts) * 256 + blockIdx.x * 8 + 2 * tig;
        float mean = acc[0][0][rh * 2]     + pp[0] + bms;
        float lv   = acc[0][0][rh * 2 + 1] + pp[1] + bvs;
        float sd = __expf(0.5f * fminf(fmaxf(lv, -80.f), 80.f));
        float nz = noise[((size_t)b * T + ts) * S + s];
        g_z[(size_t)(ts + 1) * 16384 + (s >> 5) * 4096 + imgoff(b, s & 31)] =
            t32(nz * sd + mean);
        kl += sd * sd + mean * mean - 0.5f * lv - 0.5f;
    }
    #pragma unroll
    for (int o = 16; o; o >>= 1) kl += __shfl_down_sync(0xffffffffu, kl, o);
    if (t == 0) klw[w] = (double)kl;
    __syncthreads();
    if (tid == 0) {
        double ssum = 0.0;
        #pragma unroll
        for (int i = 0; i < 8; i++) ssum += klw[i];
        g_klpart[(size_t)ts * 32 + blockIdx.x] = ssum;
    }
}

// ======================= postx: P = X @ Wmv[:, :512]^T (all t) =======================
__global__ __launch_bounds__(256) void postx_k() {
    float acc[2][4][4];
    const float* a = g_xri + (size_t)blockIdx.y * 16 * 4096;
    gemm_bulk<64, 4, 2, 2, 4, 2, 3>(acc, a, 1 << 28, a,
                                    g_Wmvx + (size_t)blockIdx.x * 16 * 2048, 8);
    const int tid = threadIdx.x, t = tid & 31, w = tid >> 5;
    const int wm = w & 3, wn = w >> 2;
    const int nb = blockIdx.x * 64, rb = blockIdx.y * 128;
    #pragma unroll
    for (int mt = 0; mt < 2; mt++)
        #pragma unroll
        for (int nt = 0; nt < 4; nt++)
            #pragma unroll
            for (int rh = 0; rh < 2; rh++) {
                int row = rb + wm * 32 + mt * 16 + (t >> 2) + rh * 8;
                int col = nb + wn * 32 + nt * 8 + 2 * (t & 3);
                *(float2*)&g_P[(size_t)row * 256 + col] =
                    make_float2(acc[mt][nt][rh * 2], acc[mt][nt][rh * 2 + 1]);
            }
}

// ======================= decoder =======================
__global__ __launch_bounds__(256) void dec1_k(const float* __restrict__ bd1) {
    float acc[2][4][4];
    const float* a = g_z + (size_t)(blockIdx.y + 1) * 16384;
    gemm_bulk<64, 4, 2, 2, 4, 1, 3>(acc, a, 1 << 28, a,
                                    g_Wd1i + (size_t)blockIdx.x * 4 * 2048, 4);
    const int tid = threadIdx.x, t = tid & 31, w = tid >> 5;
    const int wm = w & 3, wn = w >> 2;
    const int nb = blockIdx.x * 64, rb = blockIdx.y * 128;
    #pragma unroll
    for (int mt = 0; mt < 2; mt++)
        #pragma unroll
        for (int nt = 0; nt < 4; nt++)
            #pragma unroll
            for (int rh = 0; rh < 2; rh++) {
                int row = rb + wm * 32 + mt * 16 + (t >> 2) + rh * 8;   // t*128+b
                int col = nb + wn * 32 + nt * 8 + 2 * (t & 3);
                float v0 = fmaxf(acc[mt][nt][rh * 2]     + bd1[col],     0.f);
                float v1 = fmaxf(acc[mt][nt][rh * 2 + 1] + bd1[col + 1], 0.f);
                int rt = row >> 7, rr = row & 127, cc = col >> 5, kc = col & 31;
                *(float2*)&g_hid[((size_t)(rt * 32 + cc) << 12) + imgoff(rr, kc)] =
                    make_float2(t32(v0), t32(v1));
            }
}

__global__ __launch_bounds__(256) void dec2_k(const float* __restrict__ bd2,
                                              float* __restrict__ out) {
    float acc[2][4][4];
    const float* a = g_hid + (size_t)blockIdx.y * 32 * 4096;
    gemm_bulk<64, 4, 2, 2, 4, 2, 3>(acc, a, 1 << 28, a,
                                    g_Wd2i + (size_t)blockIdx.x * 32 * 2048, 16);
    const int tid = threadIdx.x, t = tid & 31, w = tid >> 5;
    const int wm = w & 3, wn = w >> 2;
    const int nb = blockIdx.x * 64, rb = blockIdx.y * 128;
    #pragma unroll
    for (int mt = 0; mt < 2; mt++)
        #pragma unroll
        for (int nt = 0; nt < 4; nt++)
            #pragma unroll
            for (int rh = 0; rh < 2; rh++) {
                int row = rb + wm * 32 + mt * 16 + (t >> 2) + rh * 8;   // t*128+b
                int col = nb + wn * 32 + nt * 8 + 2 * (t & 3);
                int tt = row >> 7, bb = row & 127;
                float v0 = acc[mt][nt][rh * 2]     + bd2[col];
                float v1 = acc[mt][nt][rh * 2 + 1] + bd2[col + 1];
                *(float2*)&out[((size_t)bb * T + tt) * DIN + col] = make_float2(v0, v1);
            }
}

// ======================= final KL reduce =======================
__global__ void kl_kernel(float* __restrict__ out) {
    __shared__ double red[256];
    int tid = threadIdx.x;
    double ssum = 0.0;
    for (int i = tid; i < T * 32; i += 256) ssum += g_klpart[i];
    red[tid] = ssum;
    __syncthreads();
    for (int off = 128; off; off >>= 1) {
        if (tid < off) red[tid] += red[tid + off];
        __syncthreads();
    }
    if (tid == 0) out[(size_t)B * T * DIN] = (float)red[0];
}

// ======================= host =======================
extern "C" void kernel_launch(void* const* d_in, const int* in_sizes, int n_in,
                              void* d_out, int out_size)
{
    const float* x     = (const float*)d_in[0];
    const float* noise = (const float*)d_in[1];
    const float* Wih   = (const float*)d_in[2];
    const float* Whh   = (const float*)d_in[3];
    const float* bih   = (const float*)d_in[4];
    const float* bhh   = (const float*)d_in[5];
    const float* Wm    = (const float*)d_in[6];
    const float* bm    = (const float*)d_in[7];
    const float* Wv    = (const float*)d_in[8];
    const float* bv    = (const float*)d_in[9];
    const float* Wd1   = (const float*)d_in[10];
    const float* bd1   = (const float*)d_in[11];
    const float* Wd2   = (const float*)d_in[12];
    const float* bd2   = (const float*)d_in[13];
    float* out = (float*)d_out;

    const int SM_BIG  = 128 + 3 * (2 * 16384 + 2 * 8192);   // 147584
    const int SM_POST = 128 + 3 * (2 * 16384 + 2 * 1024);   // 104576
    const int SM_DEC1 = 128 + 3 * (16384 + 8192);           //  73856
    cudaFuncSetAttribute(lstm_k,  cudaFuncAttributeMaxDynamicSharedMemorySize, SM_BIG);
    cudaFuncSetAttribute(post_k,  cudaFuncAttributeMaxDynamicSharedMemorySize, SM_POST);
    cudaFuncSetAttribute(postx_k, cudaFuncAttributeMaxDynamicSharedMemorySize, SM_BIG);
    cudaFuncSetAttribute(dec1_k,  cudaFuncAttributeMaxDynamicSharedMemorySize, SM_DEC1);
    cudaFuncSetAttribute(dec2_k,  cudaFuncAttributeMaxDynamicSharedMemorySize, SM_BIG);

    float *p_z, *p_h;
    cudaGetSymbolAddress((void**)&p_z, g_z);
    cudaGetSymbolAddress((void**)&p_h, g_h);

    init_kernel<<<256, 256>>>();
    prepack_kernel<<<1024, 256>>>(x, Wih, Whh, bih, bhh, Wm, Wv, Wd1, Wd2);
    postx_k<<<dim3(4, 256), 256, SM_BIG>>>();

    for (int t = 0; t < T; t++) {
        float* hin  = p_h + (size_t)(t & 1) * B * H;
        float* hout = p_h + (size_t)((t + 1) & 1) * B * H;
        lstm_k<<<64, 256, SM_BIG>>>(p_z + (size_t)t * 16384, hin, hout);
        post_k<<<32, 256, SM_POST>>>(noise, bm, bv, hout, t);
    }
    dec1_k<<<dim3(16, 256), 256, SM_DEC1>>>(bd1);
    dec2_k<<<dim3(8, 256), 256, SM_BIG>>>(bd2, out);
    kl_kernel<<<1, 256>>>(out);
}